// round 11
// baseline (speedup 1.0000x reference)
#include <cuda_runtime.h>

// Problem constants (fixed by the reference)
#define SLEN 4096
#define NSTR 4
#define DIMV 1024
#define D4   256          // DIMV / 4 (float4)
#define NCH  128          // s-chunks for pass-1 reduction
#define SPC  32           // SLEN / NCH
#define EPSV 1e-6f
#define NFOLD 256         // fold blocks inside k_mix_fused (64 k-values each)

// Deterministic scratch (no cudaMalloc allowed)
__device__ float g_partials[NCH * NSTR * NSTR * DIMV]; // [chunk][b][n][d]  (8 MB)
__device__ float g_rawp[NFOLD * 24];                   // per-block partial raw[b][j]
__device__ float g_ssqp[NFOLD];                        // per-block partial ssq
__device__ float g_coefs[NSTR * 24];                   // per-b: pre[4], post[4], res[16]
__device__ int   g_sem  = 0;                           // fold semaphore (self-resetting)
__device__ int   g_flag = 0;                           // coefs-ready flag (reset in kernel A)

// ---------------------------------------------------------------------------
// Kernel A: partial sums of H over s within a chunk. (measured 43.4us, 78% DRAM)
// grid = (NCH, NSTR, NSTR) = 2048 blocks, block = 256. Also resets g_flag.
// ---------------------------------------------------------------------------
__global__ __launch_bounds__(256) void k_reduce1(const float4* __restrict__ H4) {
    if (blockIdx.x == 0 && blockIdx.y == 0 && blockIdx.z == 0 && threadIdx.x == 0)
        g_flag = 0;   // visible to kernel B via the kernel boundary

    const int t = threadIdx.x;          // d4 index
    const int c = blockIdx.x;           // s-chunk
    const int n = blockIdx.y;
    const int b = blockIdx.z;
    const float4* p = H4 + ((size_t)(b * SLEN + c * SPC) * NSTR + n) * D4 + t;
    const size_t stride = (size_t)NSTR * D4;   // one s step

    float4 a0 = make_float4(0.f,0.f,0.f,0.f), a1 = a0, a2 = a0, a3 = a0;
    #pragma unroll
    for (int i = 0; i < SPC; i += 4) {
        float4 v0 = p[(size_t)(i+0) * stride];
        float4 v1 = p[(size_t)(i+1) * stride];
        float4 v2 = p[(size_t)(i+2) * stride];
        float4 v3 = p[(size_t)(i+3) * stride];
        a0.x += v0.x; a0.y += v0.y; a0.z += v0.z; a0.w += v0.w;
        a1.x += v1.x; a1.y += v1.y; a1.z += v1.z; a1.w += v1.w;
        a2.x += v2.x; a2.y += v2.y; a2.z += v2.z; a2.w += v2.w;
        a3.x += v3.x; a3.y += v3.y; a3.z += v3.z; a3.w += v3.w;
    }
    float4 r;
    r.x = (a0.x + a1.x) + (a2.x + a3.x);
    r.y = (a0.y + a1.y) + (a2.y + a3.y);
    r.z = (a0.z + a1.z) + (a2.z + a3.z);
    r.w = (a0.w + a1.w) + (a2.w + a3.w);
    float4* out = reinterpret_cast<float4*>(g_partials);
    out[((c * NSTR + b) * NSTR + n) * D4 + t] = r;
}

// ---------------------------------------------------------------------------
// Kernel B: fused coefs + mix. Blocks [0, NFOLD) first fold partials -> raw
// GEMV partials; last fold block finalizes (sigmoid/normalize/sinkhorn),
// publishes g_coefs with a release flag. All blocks then (acquire-)wait on
// the flag and do their k_mix work. Non-fold blocks issue their H/BO loads
// BEFORE waiting so the memory ramp hides the coefs latency.
// grid = 16384, block = 256. All reductions fixed-order -> deterministic.
// ---------------------------------------------------------------------------
__global__ __launch_bounds__(256, 6) void k_mix_fused(
    const float4* __restrict__ H4,
    const float4* __restrict__ BO4,
    float4* __restrict__ out4,
    const float* __restrict__ phi,
    const float* __restrict__ pre_base,
    const float* __restrict__ post_base,
    const float* __restrict__ res_base,
    const float* __restrict__ a_pre,
    const float* __restrict__ a_post,
    const float* __restrict__ a_res)
{
    __shared__ float c[24];
    const int t  = threadIdx.x;
    const int bs = blockIdx.x;          // b*4096 + s
    const int b  = bs >> 12;
    const bool isFold = (blockIdx.x < NFOLD);

    float4 h0, h1, h2, h3, bo;
    const size_t hb = (size_t)bs * (NSTR * D4) + t;

    if (!isFold) {
        // prefetch mix inputs (independent of coefs) before waiting
        h0 = H4[hb];
        h1 = H4[hb + D4];
        h2 = H4[hb + 2 * D4];
        h3 = H4[hb + 3 * D4];
        bo = BO4[(size_t)bs * D4 + t];
    } else {
        // ---------------- fold stage (identical math to k_coefs) ----------
        __shared__ float foldS[4][64];
        __shared__ float wr[2][24];
        __shared__ float wssq[2];
        __shared__ int   isLast;

        const int tc = t >> 6;                    // chunk group 0..3
        const int tk = t & 63;                    // k within block
        const int k  = blockIdx.x * 64 + tk;      // global (b,m) index

        {
            float s0 = 0.f, s1 = 0.f, s2 = 0.f, s3 = 0.f;
            const int c0 = tc * 32;
            #pragma unroll
            for (int cc = 0; cc < 32; cc += 4) {
                s0 += g_partials[(c0 + cc + 0) * 16384 + k];
                s1 += g_partials[(c0 + cc + 1) * 16384 + k];
                s2 += g_partials[(c0 + cc + 2) * 16384 + k];
                s3 += g_partials[(c0 + cc + 3) * 16384 + k];
            }
            foldS[tc][tk] = ((s0 + s1) + (s2 + s3));
        }
        __syncthreads();

        if (t < 64) {
            const int w = t >> 5, lane = t & 31;
            const float xv = ((foldS[0][t] + foldS[1][t]) + (foldS[2][t] + foldS[3][t]))
                           * (1.0f / (float)SLEN);
            const int mrow = (blockIdx.x * 64 + t) & 4095;

            float a[24];
            const float4* prow = reinterpret_cast<const float4*>(phi + (size_t)mrow * 24);
            #pragma unroll
            for (int q = 0; q < 6; q++) {
                float4 pv = prow[q];
                a[q*4+0] = xv * pv.x;
                a[q*4+1] = xv * pv.y;
                a[q*4+2] = xv * pv.z;
                a[q*4+3] = xv * pv.w;
            }
            float ssq = xv * xv;

            #pragma unroll
            for (int off = 16; off > 0; off >>= 1) {
                #pragma unroll
                for (int j = 0; j < 24; j++)
                    a[j] += __shfl_down_sync(0xffffffffu, a[j], off);
                ssq += __shfl_down_sync(0xffffffffu, ssq, off);
            }
            if (lane == 0) {
                #pragma unroll
                for (int j = 0; j < 24; j++) wr[w][j] = a[j];
                wssq[w] = ssq;
            }
        }
        __syncthreads();

        if (t < 24) g_rawp[blockIdx.x * 24 + t] = wr[0][t] + wr[1][t];
        if (t == 31) g_ssqp[blockIdx.x] = wssq[0] + wssq[1];

        __threadfence();
        __syncthreads();
        if (t == 0) {
            int prev = atomicAdd(&g_sem, 1);
            isLast = (prev == NFOLD - 1);
        }
        __syncthreads();

        if (isLast) {
            __shared__ float rawS[96];
            __shared__ float ssqS[4];
            if (t < 96) {
                const int b2 = t / 24, j = t - b2 * 24;
                float v = 0.f;
                #pragma unroll 16
                for (int blk = 0; blk < 64; blk++)
                    v += g_rawp[(b2 * 64 + blk) * 24 + j];
                rawS[t] = v;
            }
            if (t >= 96 && t < 100) {
                const int b2 = t - 96;
                float v = 0.f;
                #pragma unroll 16
                for (int blk = 0; blk < 64; blk++)
                    v += g_ssqp[b2 * 64 + blk];
                ssqS[b2] = v;
            }
            if (t == 128) g_sem = 0;   // reset for next graph replay
            __syncthreads();

            if (t < 4) {
                const int b2 = t;
                float inv_rms = rsqrtf(ssqS[b2] * (1.0f / 4096.0f) + EPSV);
                float ap  = a_pre[0]  * inv_rms;
                float apo = a_post[0] * inv_rms;
                float ar  = a_res[0]  * inv_rms;
                const float* raw = &rawS[b2 * 24];

                float pre[4], sum = 0.f;
                #pragma unroll
                for (int j = 0; j < 4; j++) {
                    float v = fmaf(ap, raw[j], pre_base[j]);
                    v = 1.0f / (1.0f + expf(-v));
                    pre[j] = v; sum += v;
                }
                float inv = 1.0f / (sum + EPSV);

                float post[4];
                #pragma unroll
                for (int j = 0; j < 4; j++) {
                    float v = fmaf(apo, raw[4 + j], post_base[j]);
                    post[j] = 2.0f / (1.0f + expf(-v));
                }

                float P[16];
                #pragma unroll
                for (int j = 0; j < 16; j++)
                    P[j] = fabsf(fmaf(ar, raw[8 + j], res_base[j])) + EPSV;
                for (int it = 0; it < 20; it++) {
                    #pragma unroll
                    for (int r2 = 0; r2 < 4; r2++) {
                        float rs = (P[4*r2] + P[4*r2+1]) + (P[4*r2+2] + P[4*r2+3]) + EPSV;
                        float ir = 1.0f / rs;
                        P[4*r2] *= ir; P[4*r2+1] *= ir; P[4*r2+2] *= ir; P[4*r2+3] *= ir;
                    }
                    #pragma unroll
                    for (int cI = 0; cI < 4; cI++) {
                        float cs = (P[cI] + P[4+cI]) + (P[8+cI] + P[12+cI]) + EPSV;
                        float ic = 1.0f / cs;
                        P[cI] *= ic; P[4+cI] *= ic; P[8+cI] *= ic; P[12+cI] *= ic;
                    }
                }

                float* o = &g_coefs[b2 * 24];
                #pragma unroll
                for (int j = 0; j < 4; j++)  o[j]     = pre[j] * inv;
                #pragma unroll
                for (int j = 0; j < 4; j++)  o[4 + j] = post[j];
                #pragma unroll
                for (int j = 0; j < 16; j++) o[8 + j] = P[j];
            }
            __syncthreads();
            if (t == 0) {
                __threadfence();               // publish coefs
                atomicExch(&g_flag, 1);        // release
            }
        }
    }

    // ---------------- wait for coefs (acquire) ----------------------------
    if (t == 0) {
        int f;
        do {
            asm volatile("ld.global.acquire.gpu.b32 %0, [%1];"
                         : "=r"(f) : "l"(&g_flag) : "memory");
            if (!f) __nanosleep(64);
        } while (!f);
    }
    __syncthreads();

    if (t < 24) c[t] = g_coefs[b * 24 + t];
    __syncthreads();

    if (isFold) {   // fold blocks load their mix inputs now (registers reused)
        h0 = H4[hb];
        h1 = H4[hb + D4];
        h2 = H4[hb + 2 * D4];
        h3 = H4[hb + 3 * D4];
        bo = BO4[(size_t)bs * D4 + t];
    }

    // ---------------- mix + residual + pack --------------------------------
    const size_t ob = (size_t)bs * (5 * D4) + t;

    float4 r;
    r.x = fmaf(c[0], h0.x, fmaf(c[1], h1.x, fmaf(c[2], h2.x, c[3] * h3.x)));
    r.y = fmaf(c[0], h0.y, fmaf(c[1], h1.y, fmaf(c[2], h2.y, c[3] * h3.y)));
    r.z = fmaf(c[0], h0.z, fmaf(c[1], h1.z, fmaf(c[2], h2.z, c[3] * h3.z)));
    r.w = fmaf(c[0], h0.w, fmaf(c[1], h1.w, fmaf(c[2], h2.w, c[3] * h3.w)));
    out4[ob] = r;

    #pragma unroll
    for (int n = 0; n < 4; n++) {
        float r0 = c[8 + 4*n], r1 = c[9 + 4*n], r2 = c[10 + 4*n], r3 = c[11 + 4*n];
        float pp = c[4 + n];
        float4 o;
        o.x = fmaf(r0, h0.x, fmaf(r1, h1.x, fmaf(r2, h2.x, fmaf(r3, h3.x, pp * bo.x))));
        o.y = fmaf(r0, h0.y, fmaf(r1, h1.y, fmaf(r2, h2.y, fmaf(r3, h3.y, pp * bo.y))));
        o.z = fmaf(r0, h0.z, fmaf(r1, h1.z, fmaf(r2, h2.z, fmaf(r3, h3.z, pp * bo.z))));
        o.w = fmaf(r0, h0.w, fmaf(r1, h1.w, fmaf(r2, h2.w, fmaf(r3, h3.w, pp * bo.w))));
        out4[ob + (size_t)(1 + n) * D4] = o;
    }
}

// ---------------------------------------------------------------------------
// Inputs (metadata order): H, branch_output, phi, H_pre_base, H_post_base,
//                          H_res_base, alpha_pre, alpha_post, alpha_res
// ---------------------------------------------------------------------------
extern "C" void kernel_launch(void* const* d_in, const int* in_sizes, int n_in,
                              void* d_out, int out_size) {
    (void)in_sizes; (void)n_in; (void)out_size;
    const float4* H4  = (const float4*)d_in[0];
    const float4* BO4 = (const float4*)d_in[1];
    const float* phi  = (const float*)d_in[2];
    const float* preb = (const float*)d_in[3];
    const float* postb= (const float*)d_in[4];
    const float* resb = (const float*)d_in[5];
    const float* apre = (const float*)d_in[6];
    const float* apost= (const float*)d_in[7];
    const float* ares = (const float*)d_in[8];

    dim3 g1(NCH, NSTR, NSTR);
    k_reduce1<<<g1, 256>>>(H4);
    k_mix_fused<<<16384, 256>>>(H4, BO4, (float4*)d_out,
                                phi, preb, postb, resb, apre, apost, ares);
}

// round 12
// speedup vs baseline: 1.0785x; 1.0785x over previous
#include <cuda_runtime.h>

// Problem constants (fixed by the reference)
#define SLEN 4096
#define NSTR 4
#define DIMV 1024
#define D4   256
#define GRID 592          // 4 blocks x 148 SMs: guaranteed co-resident
#define NTHR 256
#define NCHP 256          // phase-1 chunks
#define SPCP 16           // s per chunk
#define NUNITS 4096       // NCHP * 16 (b,n combos)
#define NFB  512          // fold blocks (32 k each)
#define EPSV 1e-6f

// Deterministic scratch (no cudaMalloc allowed)
__device__ float g_part[NUNITS * DIMV];   // [u][d], u = (b*4+n)*256 + c  (16 MB)
__device__ float g_rawp[NFB * 24];
__device__ float g_ssqp[NFB];
__device__ float g_coefs[NSTR * 24];
__device__ unsigned g_bar_cnt = 0;        // returns to 0 after each barrier
__device__ unsigned g_bar_gen = 0;        // monotonic across replays

// Sense-reversing grid barrier. Safe across graph replays: every block reads
// the current generation at kernel start (all blocks read the same value,
// since no barrier can complete before all 592 arrive).
__device__ __forceinline__ void gbar(unsigned* s_gen) {
    __syncthreads();
    if (threadIdx.x == 0) {
        unsigned target = *s_gen + 1;
        __threadfence();
        unsigned old = atomicAdd(&g_bar_cnt, 1);
        if (old == GRID - 1) {
            g_bar_cnt = 0;
            __threadfence();
            atomicExch(&g_bar_gen, target);
        } else {
            unsigned cur;
            for (;;) {
                asm volatile("ld.global.acquire.gpu.b32 %0, [%1];"
                             : "=r"(cur) : "l"(&g_bar_gen) : "memory");
                if ((int)(cur - target) >= 0) break;
                __nanosleep(64);
            }
        }
        *s_gen = target;
    }
    __syncthreads();
}

__global__ __launch_bounds__(NTHR, 4) void k_all(
    const float4* __restrict__ H4,
    const float4* __restrict__ BO4,
    float4* __restrict__ out4,
    const float* __restrict__ phi,
    const float* __restrict__ pre_base,
    const float* __restrict__ post_base,
    const float* __restrict__ res_base,
    const float* __restrict__ a_pre,
    const float* __restrict__ a_post,
    const float* __restrict__ a_res)
{
    __shared__ unsigned s_gen;
    __shared__ float sums[8][32];
    __shared__ float cS[96];
    __shared__ float rawS[96];
    __shared__ float ssqS[4];

    const int t = threadIdx.x;
    if (t == 0) s_gen = atomicAdd(&g_bar_gen, 0u);   // snapshot generation
    __syncthreads();

    // ================= Phase 1: reduce H over s (grid-stride units) ========
    // unit u: chunk c = u & 255 (fast across adjacent blocks), bn = u >> 8.
    for (int u = blockIdx.x; u < NUNITS; u += GRID) {
        const int c  = u & 255;
        const int bn = u >> 8;
        const int b  = bn >> 2, n = bn & 3;
        const float4* p = H4 + ((size_t)(b * SLEN + c * SPCP) * NSTR + n) * D4 + t;
        const size_t stride = (size_t)NSTR * D4;

        float4 a0 = make_float4(0.f,0.f,0.f,0.f), a1 = a0, a2 = a0, a3 = a0;
        #pragma unroll
        for (int i = 0; i < SPCP; i += 4) {
            float4 v0 = p[(size_t)(i+0) * stride];
            float4 v1 = p[(size_t)(i+1) * stride];
            float4 v2 = p[(size_t)(i+2) * stride];
            float4 v3 = p[(size_t)(i+3) * stride];
            a0.x += v0.x; a0.y += v0.y; a0.z += v0.z; a0.w += v0.w;
            a1.x += v1.x; a1.y += v1.y; a1.z += v1.z; a1.w += v1.w;
            a2.x += v2.x; a2.y += v2.y; a2.z += v2.z; a2.w += v2.w;
            a3.x += v3.x; a3.y += v3.y; a3.z += v3.z; a3.w += v3.w;
        }
        float4 r;
        r.x = (a0.x + a1.x) + (a2.x + a3.x);
        r.y = (a0.y + a1.y) + (a2.y + a3.y);
        r.z = (a0.z + a1.z) + (a2.z + a3.z);
        r.w = (a0.w + a1.w) + (a2.w + a3.w);
        reinterpret_cast<float4*>(g_part)[(size_t)u * D4 + t] = r;
    }
    gbar(&s_gen);   // B1: partials complete

    // ================= Phase 2: fold + GEMV (blocks 0..NFB-1) ==============
    if (blockIdx.x < NFB) {
        const int fb = blockIdx.x;
        const int g  = t >> 5, kl = t & 31;
        const int k  = fb * 32 + kl;           // 0..16383 (b,m)
        const int b  = k >> 12, m = k & 4095;
        const int n  = m >> 10, d = m & 1023;
        const float* base = g_part + ((size_t)((b * 4 + n) * 256 + g * 32)) * 1024 + d;

        float s0 = 0.f, s1 = 0.f, s2 = 0.f, s3 = 0.f;
        #pragma unroll
        for (int cc = 0; cc < 32; cc += 4) {
            s0 += base[(cc+0) * 1024];
            s1 += base[(cc+1) * 1024];
            s2 += base[(cc+2) * 1024];
            s3 += base[(cc+3) * 1024];
        }
        sums[g][kl] = (s0 + s1) + (s2 + s3);
        __syncthreads();

        if (t < 32) {
            float tot = ((sums[0][t] + sums[1][t]) + (sums[2][t] + sums[3][t]))
                      + ((sums[4][t] + sums[5][t]) + (sums[6][t] + sums[7][t]));
            const float xv = tot * (1.0f / (float)SLEN);
            const int m2 = (fb * 32 + t) & 4095;

            float a[24];
            const float4* prow = reinterpret_cast<const float4*>(phi + (size_t)m2 * 24);
            #pragma unroll
            for (int q = 0; q < 6; q++) {
                float4 pv = prow[q];
                a[q*4+0] = xv * pv.x;
                a[q*4+1] = xv * pv.y;
                a[q*4+2] = xv * pv.z;
                a[q*4+3] = xv * pv.w;
            }
            float ssq = xv * xv;

            #pragma unroll
            for (int off = 16; off > 0; off >>= 1) {
                #pragma unroll
                for (int j = 0; j < 24; j++)
                    a[j] += __shfl_down_sync(0xffffffffu, a[j], off);
                ssq += __shfl_down_sync(0xffffffffu, ssq, off);
            }
            if (t == 0) {
                #pragma unroll
                for (int j = 0; j < 24; j++) g_rawp[fb * 24 + j] = a[j];
                g_ssqp[fb] = ssq;
            }
        }
    }
    gbar(&s_gen);   // B2: raw partials complete

    // ================= Phase 2b: finalizer (block 0 only) ===================
    if (blockIdx.x == 0) {
        if (t < 96) {
            const int bb = t / 24, j = t - bb * 24;  // batch bb owns fb [bb*128, bb*128+128)
            float v = 0.f;
            #pragma unroll 16
            for (int blk = 0; blk < 128; blk++)
                v += g_rawp[(bb * 128 + blk) * 24 + j];
            rawS[t] = v;
        }
        if (t >= 96 && t < 100) {
            const int bb = t - 96;
            float v = 0.f;
            #pragma unroll 16
            for (int blk = 0; blk < 128; blk++)
                v += g_ssqp[bb * 128 + blk];
            ssqS[bb] = v;
        }
        __syncthreads();

        if (t < 4) {
            const int bb = t;
            float inv_rms = rsqrtf(ssqS[bb] * (1.0f / 4096.0f) + EPSV);
            float ap  = a_pre[0]  * inv_rms;
            float apo = a_post[0] * inv_rms;
            float ar  = a_res[0]  * inv_rms;
            const float* raw = &rawS[bb * 24];

            float pre[4], sum = 0.f;
            #pragma unroll
            for (int j = 0; j < 4; j++) {
                float v = fmaf(ap, raw[j], pre_base[j]);
                v = 1.0f / (1.0f + expf(-v));
                pre[j] = v; sum += v;
            }
            float inv = 1.0f / (sum + EPSV);

            float post[4];
            #pragma unroll
            for (int j = 0; j < 4; j++) {
                float v = fmaf(apo, raw[4 + j], post_base[j]);
                post[j] = 2.0f / (1.0f + expf(-v));
            }

            float P[16];
            #pragma unroll
            for (int j = 0; j < 16; j++)
                P[j] = fabsf(fmaf(ar, raw[8 + j], res_base[j])) + EPSV;
            for (int it = 0; it < 20; it++) {
                #pragma unroll
                for (int r2 = 0; r2 < 4; r2++) {
                    float rs = (P[4*r2] + P[4*r2+1]) + (P[4*r2+2] + P[4*r2+3]) + EPSV;
                    float ir = 1.0f / rs;
                    P[4*r2] *= ir; P[4*r2+1] *= ir; P[4*r2+2] *= ir; P[4*r2+3] *= ir;
                }
                #pragma unroll
                for (int cI = 0; cI < 4; cI++) {
                    float cs = (P[cI] + P[4+cI]) + (P[8+cI] + P[12+cI]) + EPSV;
                    float ic = 1.0f / cs;
                    P[cI] *= ic; P[4+cI] *= ic; P[8+cI] *= ic; P[12+cI] *= ic;
                }
            }

            float* o = &g_coefs[bb * 24];
            #pragma unroll
            for (int j = 0; j < 4; j++)  o[j]     = pre[j] * inv;
            #pragma unroll
            for (int j = 0; j < 4; j++)  o[4 + j] = post[j];
            #pragma unroll
            for (int j = 0; j < 16; j++) o[8 + j] = P[j];
        }
    }
    gbar(&s_gen);   // B3: coefs published

    // ================= Phase 3: mix + residual + pack (grid-stride) =========
    for (int i = t; i < 96; i += NTHR) cS[i] = g_coefs[i];
    __syncthreads();

    for (int bs = blockIdx.x; bs < 16384; bs += GRID) {
        const float* c = cS + ((bs >> 12) * 24);
        const size_t hb = (size_t)bs * (NSTR * D4) + t;
        float4 h0 = H4[hb];
        float4 h1 = H4[hb + D4];
        float4 h2 = H4[hb + 2 * D4];
        float4 h3 = H4[hb + 3 * D4];
        float4 bo = BO4[(size_t)bs * D4 + t];

        const size_t ob = (size_t)bs * (5 * D4) + t;

        float4 r;
        r.x = fmaf(c[0], h0.x, fmaf(c[1], h1.x, fmaf(c[2], h2.x, c[3] * h3.x)));
        r.y = fmaf(c[0], h0.y, fmaf(c[1], h1.y, fmaf(c[2], h2.y, c[3] * h3.y)));
        r.z = fmaf(c[0], h0.z, fmaf(c[1], h1.z, fmaf(c[2], h2.z, c[3] * h3.z)));
        r.w = fmaf(c[0], h0.w, fmaf(c[1], h1.w, fmaf(c[2], h2.w, c[3] * h3.w)));
        out4[ob] = r;

        #pragma unroll
        for (int n = 0; n < 4; n++) {
            float r0 = c[8 + 4*n], r1 = c[9 + 4*n], r2 = c[10 + 4*n], r3 = c[11 + 4*n];
            float pp = c[4 + n];
            float4 o;
            o.x = fmaf(r0, h0.x, fmaf(r1, h1.x, fmaf(r2, h2.x, fmaf(r3, h3.x, pp * bo.x))));
            o.y = fmaf(r0, h0.y, fmaf(r1, h1.y, fmaf(r2, h2.y, fmaf(r3, h3.y, pp * bo.y))));
            o.z = fmaf(r0, h0.z, fmaf(r1, h1.z, fmaf(r2, h2.z, fmaf(r3, h3.z, pp * bo.z))));
            o.w = fmaf(r0, h0.w, fmaf(r1, h1.w, fmaf(r2, h2.w, fmaf(r3, h3.w, pp * bo.w))));
            out4[ob + (size_t)(1 + n) * D4] = o;
        }
    }
}

// ---------------------------------------------------------------------------
// Inputs (metadata order): H, branch_output, phi, H_pre_base, H_post_base,
//                          H_res_base, alpha_pre, alpha_post, alpha_res
// ---------------------------------------------------------------------------
extern "C" void kernel_launch(void* const* d_in, const int* in_sizes, int n_in,
                              void* d_out, int out_size) {
    (void)in_sizes; (void)n_in; (void)out_size;
    const float4* H4  = (const float4*)d_in[0];
    const float4* BO4 = (const float4*)d_in[1];
    const float* phi  = (const float*)d_in[2];
    const float* preb = (const float*)d_in[3];
    const float* postb= (const float*)d_in[4];
    const float* resb = (const float*)d_in[5];
    const float* apre = (const float*)d_in[6];
    const float* apost= (const float*)d_in[7];
    const float* ares = (const float*)d_in[8];

    k_all<<<GRID, NTHR>>>(H4, BO4, (float4*)d_out,
                          phi, preb, postb, resb, apre, apost, ares);
}

// round 13
// speedup vs baseline: 1.0992x; 1.0193x over previous
#include <cuda_runtime.h>

// Problem constants (fixed by the reference)
#define SLEN 4096
#define NSTR 4
#define DIMV 1024
#define D4   256
#define GRID 888          // 6 blocks x 148 SMs: guaranteed co-resident at <=40 regs
#define NTHR 256
#define SPCP 16           // s-rows per phase-1 unit
#define NUNITS 4096       // (4 batches * 256 chunks) * 4 streams
#define NFB  512          // fold blocks (32 k each)
#define EPSV 1e-6f

// Deterministic scratch (no cudaMalloc allowed)
__device__ float g_part[NUNITS * DIMV];   // [u][d], u = ((b*256+c)*4+n)  (16 MB)
__device__ float g_rawp[NFB * 24];
__device__ float g_ssqp[NFB];
__device__ float g_coefs[NSTR * 24];
__device__ unsigned g_bar_cnt = 0;        // returns to 0 after each barrier
__device__ unsigned g_bar_gen = 0;        // monotonic across replays

// Grid barrier (proven in R12). Generation is monotonic across graph replays.
__device__ __forceinline__ void gbar(unsigned* s_gen) {
    __syncthreads();
    if (threadIdx.x == 0) {
        unsigned target = *s_gen + 1;
        __threadfence();
        unsigned old = atomicAdd(&g_bar_cnt, 1);
        if (old == GRID - 1) {
            g_bar_cnt = 0;
            __threadfence();
            atomicExch(&g_bar_gen, target);
        } else {
            unsigned cur;
            for (;;) {
                asm volatile("ld.global.acquire.gpu.b32 %0, [%1];"
                             : "=r"(cur) : "l"(&g_bar_gen) : "memory");
                if ((int)(cur - target) >= 0) break;
                __nanosleep(64);
            }
        }
        *s_gen = target;
    }
    __syncthreads();
}

__global__ __launch_bounds__(NTHR, 6) void k_all(
    const float4* __restrict__ H4,
    const float4* __restrict__ BO4,
    float4* __restrict__ out4,
    const float* __restrict__ phi,
    const float* __restrict__ pre_base,
    const float* __restrict__ post_base,
    const float* __restrict__ res_base,
    const float* __restrict__ a_pre,
    const float* __restrict__ a_post,
    const float* __restrict__ a_res)
{
    __shared__ unsigned s_gen;
    __shared__ float sums[8][32];
    __shared__ float cS[96];
    __shared__ float rawS[96];
    __shared__ float ssqS[4];

    const int t  = threadIdx.x;
    const int bx = blockIdx.x;
    if (t == 0) s_gen = atomicAdd(&g_bar_gen, 0u);   // snapshot generation
    __syncthreads();

    // ===== Phase 1: reduce H over s. Units ascend in (b,s) so the H tail
    // (high bs) is the most recent L2 content when phase 3 starts. =========
    for (int u = bx; u < NUNITS; u += GRID) {
        const int C = u >> 2;            // global chunk 0..1023 (ascending b,s)
        const int n = u & 3;
        const int b = C >> 8, c = C & 255;
        const float4* p = H4 + ((size_t)(b * SLEN + c * SPCP) * NSTR + n) * D4 + t;

        float4 a0 = make_float4(0.f,0.f,0.f,0.f), a1 = a0, a2 = a0, a3 = a0;
        #pragma unroll
        for (int i = 0; i < SPCP; i += 4) {
            float4 v0 = p[(size_t)(i+0) * 1024];
            float4 v1 = p[(size_t)(i+1) * 1024];
            float4 v2 = p[(size_t)(i+2) * 1024];
            float4 v3 = p[(size_t)(i+3) * 1024];
            a0.x += v0.x; a0.y += v0.y; a0.z += v0.z; a0.w += v0.w;
            a1.x += v1.x; a1.y += v1.y; a1.z += v1.z; a1.w += v1.w;
            a2.x += v2.x; a2.y += v2.y; a2.z += v2.z; a2.w += v2.w;
            a3.x += v3.x; a3.y += v3.y; a3.z += v3.z; a3.w += v3.w;
        }
        float4 r;
        r.x = (a0.x + a1.x) + (a2.x + a3.x);
        r.y = (a0.y + a1.y) + (a2.y + a3.y);
        r.z = (a0.z + a1.z) + (a2.z + a3.z);
        r.w = (a0.w + a1.w) + (a2.w + a3.w);
        reinterpret_cast<float4*>(g_part)[(size_t)u * D4 + t] = r;
    }
    gbar(&s_gen);   // B1: partials complete

    // ===== Phase 2: fold 256 chunks + GEMV (blocks 0..NFB-1) ===============
    if (bx < NFB) {
        const int g  = t >> 5, kl = t & 31;
        const int k  = bx * 32 + kl;          // 0..16383 = (b, n, d)
        const int b  = k >> 12;
        const int n  = (k >> 10) & 3;
        const int d  = k & 1023;
        // u(c) = (b*256 + c)*4 + n ; address = u*1024 + d ; stride over c = 4096
        const float* base = g_part + ((size_t)((b * 256 + g * 32) * 4 + n)) * 1024 + d;

        float s0 = 0.f, s1 = 0.f, s2 = 0.f, s3 = 0.f;
        #pragma unroll
        for (int cc = 0; cc < 32; cc += 4) {
            s0 += base[(size_t)(cc+0) * 4096];
            s1 += base[(size_t)(cc+1) * 4096];
            s2 += base[(size_t)(cc+2) * 4096];
            s3 += base[(size_t)(cc+3) * 4096];
        }
        sums[g][kl] = (s0 + s1) + (s2 + s3);
        __syncthreads();

        if (t < 32) {
            float tot = ((sums[0][t] + sums[1][t]) + (sums[2][t] + sums[3][t]))
                      + ((sums[4][t] + sums[5][t]) + (sums[6][t] + sums[7][t]));
            const float xv = tot * (1.0f / (float)SLEN);
            const int m2 = (bx * 32 + t) & 4095;

            float a[24];
            const float4* prow = reinterpret_cast<const float4*>(phi + (size_t)m2 * 24);
            #pragma unroll
            for (int q = 0; q < 6; q++) {
                float4 pv = prow[q];
                a[q*4+0] = xv * pv.x;
                a[q*4+1] = xv * pv.y;
                a[q*4+2] = xv * pv.z;
                a[q*4+3] = xv * pv.w;
            }
            float ssq = xv * xv;

            #pragma unroll
            for (int off = 16; off > 0; off >>= 1) {
                #pragma unroll
                for (int j = 0; j < 24; j++)
                    a[j] += __shfl_down_sync(0xffffffffu, a[j], off);
                ssq += __shfl_down_sync(0xffffffffu, ssq, off);
            }
            if (t == 0) {
                #pragma unroll
                for (int j = 0; j < 24; j++) g_rawp[bx * 24 + j] = a[j];
                g_ssqp[bx] = ssq;
            }
        }
    }
    gbar(&s_gen);   // B2: raw partials complete

    // ===== Phase 2b: finalizer (block 0) ===================================
    if (bx == 0) {
        if (t < 96) {
            const int bb = t / 24, j = t - bb * 24;  // batch bb owns fb [bb*128, bb*128+128)
            float v = 0.f;
            #pragma unroll 16
            for (int blk = 0; blk < 128; blk++)
                v += g_rawp[(bb * 128 + blk) * 24 + j];
            rawS[t] = v;
        }
        if (t >= 96 && t < 100) {
            const int bb = t - 96;
            float v = 0.f;
            #pragma unroll 16
            for (int blk = 0; blk < 128; blk++)
                v += g_ssqp[bb * 128 + blk];
            ssqS[bb] = v;
        }
        __syncthreads();

        if (t < 4) {
            const int bb = t;
            float inv_rms = rsqrtf(ssqS[bb] * (1.0f / 4096.0f) + EPSV);
            float ap  = a_pre[0]  * inv_rms;
            float apo = a_post[0] * inv_rms;
            float ar  = a_res[0]  * inv_rms;
            const float* raw = &rawS[bb * 24];

            float pre[4], sum = 0.f;
            #pragma unroll
            for (int j = 0; j < 4; j++) {
                float v = fmaf(ap, raw[j], pre_base[j]);
                v = 1.0f / (1.0f + expf(-v));
                pre[j] = v; sum += v;
            }
            float inv = 1.0f / (sum + EPSV);

            float post[4];
            #pragma unroll
            for (int j = 0; j < 4; j++) {
                float v = fmaf(apo, raw[4 + j], post_base[j]);
                post[j] = 2.0f / (1.0f + expf(-v));
            }

            float P[16];
            #pragma unroll
            for (int j = 0; j < 16; j++)
                P[j] = fabsf(fmaf(ar, raw[8 + j], res_base[j])) + EPSV;
            for (int it = 0; it < 20; it++) {
                #pragma unroll
                for (int r2 = 0; r2 < 4; r2++) {
                    float rs = (P[4*r2] + P[4*r2+1]) + (P[4*r2+2] + P[4*r2+3]) + EPSV;
                    float ir = 1.0f / rs;
                    P[4*r2] *= ir; P[4*r2+1] *= ir; P[4*r2+2] *= ir; P[4*r2+3] *= ir;
                }
                #pragma unroll
                for (int cI = 0; cI < 4; cI++) {
                    float cs = (P[cI] + P[4+cI]) + (P[8+cI] + P[12+cI]) + EPSV;
                    float ic = 1.0f / cs;
                    P[cI] *= ic; P[4+cI] *= ic; P[8+cI] *= ic; P[12+cI] *= ic;
                }
            }

            float* o = &g_coefs[bb * 24];
            #pragma unroll
            for (int j = 0; j < 4; j++)  o[j]     = pre[j] * inv;
            #pragma unroll
            for (int j = 0; j < 4; j++)  o[4 + j] = post[j];
            #pragma unroll
            for (int j = 0; j < 16; j++) o[8 + j] = P[j];
        }
    }
    gbar(&s_gen);   // B3: coefs published

    // ===== Phase 3: mix + residual + pack, bs DESCENDING (hit warm H tail).
    // BO read evict-first, output written evict-first to protect H in L2. ===
    for (int i = t; i < 96; i += NTHR) cS[i] = g_coefs[i];
    __syncthreads();

    for (int idx = bx; idx < 16384; idx += GRID) {
        const int bs = 16383 - idx;
        const float* c = cS + ((bs >> 12) * 24);
        const size_t hb = (size_t)bs * (NSTR * D4) + t;
        float4 h0 = H4[hb];
        float4 h1 = H4[hb + D4];
        float4 h2 = H4[hb + 2 * D4];
        float4 h3 = H4[hb + 3 * D4];
        float4 bo = __ldcs(&BO4[(size_t)bs * D4 + t]);

        const size_t ob = (size_t)bs * (5 * D4) + t;

        float4 r;
        r.x = fmaf(c[0], h0.x, fmaf(c[1], h1.x, fmaf(c[2], h2.x, c[3] * h3.x)));
        r.y = fmaf(c[0], h0.y, fmaf(c[1], h1.y, fmaf(c[2], h2.y, c[3] * h3.y)));
        r.z = fmaf(c[0], h0.z, fmaf(c[1], h1.z, fmaf(c[2], h2.z, c[3] * h3.z)));
        r.w = fmaf(c[0], h0.w, fmaf(c[1], h1.w, fmaf(c[2], h2.w, c[3] * h3.w)));
        __stcs(&out4[ob], r);

        #pragma unroll
        for (int n = 0; n < 4; n++) {
            float r0 = c[8 + 4*n], r1 = c[9 + 4*n], r2 = c[10 + 4*n], r3 = c[11 + 4*n];
            float pp = c[4 + n];
            float4 o;
            o.x = fmaf(r0, h0.x, fmaf(r1, h1.x, fmaf(r2, h2.x, fmaf(r3, h3.x, pp * bo.x))));
            o.y = fmaf(r0, h0.y, fmaf(r1, h1.y, fmaf(r2, h2.y, fmaf(r3, h3.y, pp * bo.y))));
            o.z = fmaf(r0, h0.z, fmaf(r1, h1.z, fmaf(r2, h2.z, fmaf(r3, h3.z, pp * bo.z))));
            o.w = fmaf(r0, h0.w, fmaf(r1, h1.w, fmaf(r2, h2.w, fmaf(r3, h3.w, pp * bo.w))));
            __stcs(&out4[ob + (size_t)(1 + n) * D4], o);
        }
    }
}

// ---------------------------------------------------------------------------
// Inputs (metadata order): H, branch_output, phi, H_pre_base, H_post_base,
//                          H_res_base, alpha_pre, alpha_post, alpha_res
// ---------------------------------------------------------------------------
extern "C" void kernel_launch(void* const* d_in, const int* in_sizes, int n_in,
                              void* d_out, int out_size) {
    (void)in_sizes; (void)n_in; (void)out_size;
    const float4* H4  = (const float4*)d_in[0];
    const float4* BO4 = (const float4*)d_in[1];
    const float* phi  = (const float*)d_in[2];
    const float* preb = (const float*)d_in[3];
    const float* postb= (const float*)d_in[4];
    const float* resb = (const float*)d_in[5];
    const float* apre = (const float*)d_in[6];
    const float* apost= (const float*)d_in[7];
    const float* ares = (const float*)d_in[8];

    k_all<<<GRID, NTHR>>>(H4, BO4, (float4*)d_out,
                          phi, preb, postb, resb, apre, apost, ares);
}

// round 15
// speedup vs baseline: 1.1873x; 1.0801x over previous
#include <cuda_runtime.h>

// Problem constants (fixed by the reference)
#define SLEN 4096
#define NSTR 4
#define DIMV 1024
#define D4   256          // DIMV / 4 (float4)
#define NCH  64           // s-chunks: 1024 blocks (fills SMs) AND 4 MB partials (L2-hot)
#define SPC  64           // SLEN / NCH
#define EPSV 1e-6f
#define NFB  64           // fold blocks

// Deterministic scratch (no cudaMalloc allowed)
__device__ float g_partials[NCH * NSTR * NSTR * DIMV]; // [chunk][b][n][d]  (4 MB)
__device__ float g_rawp[NFB * 24];                     // per-block partial raw[b][j]
__device__ float g_ssqp[NFB];                          // per-block partial ssq
__device__ float g_coefs[NSTR * 24];                   // per-b: pre[4], post[4], res[16]
__device__ int   g_sem = 0;                            // last-block semaphore (self-resetting)

// ---------------------------------------------------------------------------
// Kernel 1: partial sums of H over s within a chunk.
// grid = (NCH, NSTR, NSTR) = 1024 blocks, block = 256 (one thread per float4).
// Same strided pattern as the measured-43.4us NCH=128 version; 1024 blocks
// = ~1772 thr/SM (87% occ) vs 512 blocks' 43%.
// ---------------------------------------------------------------------------
__global__ __launch_bounds__(256) void k_reduce1(const float4* __restrict__ H4) {
    const int t = threadIdx.x;          // d4 index
    const int c = blockIdx.x;           // s-chunk
    const int n = blockIdx.y;
    const int b = blockIdx.z;
    const float4* p = H4 + ((size_t)(b * SLEN + c * SPC) * NSTR + n) * D4 + t;
    const size_t stride = (size_t)NSTR * D4;   // one s step (1024 float4)

    float4 a0 = make_float4(0.f,0.f,0.f,0.f), a1 = a0, a2 = a0, a3 = a0;
    #pragma unroll 4
    for (int i = 0; i < SPC; i += 4) {
        float4 v0 = p[(size_t)(i+0) * stride];
        float4 v1 = p[(size_t)(i+1) * stride];
        float4 v2 = p[(size_t)(i+2) * stride];
        float4 v3 = p[(size_t)(i+3) * stride];
        a0.x += v0.x; a0.y += v0.y; a0.z += v0.z; a0.w += v0.w;
        a1.x += v1.x; a1.y += v1.y; a1.z += v1.z; a1.w += v1.w;
        a2.x += v2.x; a2.y += v2.y; a2.z += v2.z; a2.w += v2.w;
        a3.x += v3.x; a3.y += v3.y; a3.z += v3.z; a3.w += v3.w;
    }
    float4 r;
    r.x = (a0.x + a1.x) + (a2.x + a3.x);
    r.y = (a0.y + a1.y) + (a2.y + a3.y);
    r.z = (a0.z + a1.z) + (a2.z + a3.z);
    r.w = (a0.w + a1.w) + (a2.w + a3.w);
    float4* out = reinterpret_cast<float4*>(g_partials);
    out[((c * NSTR + b) * NSTR + n) * D4 + t] = r;
}

// ---------------------------------------------------------------------------
// Kernel 2 (fused): fold 64 chunk partials -> x (mean), per-block GEMV
// partials raw[b][j] = sum_m x[b,m]*phi[m,j] + partial ssq; LAST block runs
// the scalar finalizer (sigmoid / normalize / sinkhorn).
// grid = 64 blocks x 256 threads, thread-per-k; partials are 4 MB (L2-hot)
// and the read is fully coalesced. Fixed reduction order -> deterministic.
// ---------------------------------------------------------------------------
__global__ __launch_bounds__(256) void k_coefs(
    const float* __restrict__ phi,
    const float* __restrict__ pre_base,
    const float* __restrict__ post_base,
    const float* __restrict__ res_base,
    const float* __restrict__ a_pre,
    const float* __restrict__ a_post,
    const float* __restrict__ a_res)
{
    __shared__ float wr[8][24];   // per-warp raw partials
    __shared__ float wssq[8];
    __shared__ int   isLast;

    const int t = threadIdx.x;
    const int k = blockIdx.x * 256 + t;   // global index into [b][m] space, 0..16383
    const int m = k & 4095;               // index into phi rows
    const int w = t >> 5, lane = t & 31;

    // fold 64 chunk partials (coalesced, mostly L2) -> mean xv
    float s0 = 0.f, s1 = 0.f, s2 = 0.f, s3 = 0.f;
    float s4 = 0.f, s5 = 0.f, s6 = 0.f, s7 = 0.f;
    #pragma unroll 8
    for (int c = 0; c < NCH; c += 8) {
        s0 += g_partials[(c+0) * 16384 + k];
        s1 += g_partials[(c+1) * 16384 + k];
        s2 += g_partials[(c+2) * 16384 + k];
        s3 += g_partials[(c+3) * 16384 + k];
        s4 += g_partials[(c+4) * 16384 + k];
        s5 += g_partials[(c+5) * 16384 + k];
        s6 += g_partials[(c+6) * 16384 + k];
        s7 += g_partials[(c+7) * 16384 + k];
    }
    const float xv = (((s0 + s1) + (s2 + s3)) + ((s4 + s5) + (s6 + s7)))
                   * (1.0f / (float)SLEN);

    // per-thread contributions: xv * phi[m][j], j = 0..23  (6x float4)
    float a[24];
    const float4* prow = reinterpret_cast<const float4*>(phi + (size_t)m * 24);
    #pragma unroll
    for (int q = 0; q < 6; q++) {
        float4 pv = prow[q];
        a[q*4+0] = xv * pv.x;
        a[q*4+1] = xv * pv.y;
        a[q*4+2] = xv * pv.z;
        a[q*4+3] = xv * pv.w;
    }
    float ssq = xv * xv;

    // warp reduce all 25 values
    #pragma unroll
    for (int off = 16; off > 0; off >>= 1) {
        #pragma unroll
        for (int j = 0; j < 24; j++)
            a[j] += __shfl_down_sync(0xffffffffu, a[j], off);
        ssq += __shfl_down_sync(0xffffffffu, ssq, off);
    }
    if (lane == 0) {
        #pragma unroll
        for (int j = 0; j < 24; j++) wr[w][j] = a[j];
        wssq[w] = ssq;
    }
    __syncthreads();

    if (t < 24) {
        float v = (wr[0][t] + wr[1][t]) + (wr[2][t] + wr[3][t])
                + (wr[4][t] + wr[5][t]) + (wr[6][t] + wr[7][t]);
        g_rawp[blockIdx.x * 24 + t] = v;
    }
    if (t == 31) {
        g_ssqp[blockIdx.x] = (wssq[0] + wssq[1]) + (wssq[2] + wssq[3])
                           + (wssq[4] + wssq[5]) + (wssq[6] + wssq[7]);
    }

    // ---- last-block finalizer ----
    __threadfence();
    __syncthreads();
    if (t == 0) {
        int prev = atomicAdd(&g_sem, 1);
        isLast = (prev == gridDim.x - 1);
    }
    __syncthreads();
    if (!isLast) return;

    __shared__ float rawS[96];
    __shared__ float ssqS[4];
    if (t < 96) {
        const int bb = t / 24, j = t - bb * 24;   // batch bb owns blocks 16*bb..16*bb+15
        float v = 0.f;
        #pragma unroll
        for (int blk = 0; blk < 16; blk++)
            v += g_rawp[(bb * 16 + blk) * 24 + j];
        rawS[t] = v;
    }
    if (t >= 96 && t < 100) {
        const int bb = t - 96;
        float v = 0.f;
        #pragma unroll
        for (int blk = 0; blk < 16; blk++)
            v += g_ssqp[bb * 16 + blk];
        ssqS[bb] = v;
    }
    if (t == 128) g_sem = 0;   // reset for next graph replay (deterministic)
    __syncthreads();

    if (t < 4) {
        const int bb = t;
        float inv_rms = rsqrtf(ssqS[bb] * (1.0f / 4096.0f) + EPSV);
        float ap  = a_pre[0]  * inv_rms;
        float apo = a_post[0] * inv_rms;
        float ar  = a_res[0]  * inv_rms;
        const float* raw = &rawS[bb * 24];

        float pre[4], sum = 0.f;
        #pragma unroll
        for (int j = 0; j < 4; j++) {
            float v = fmaf(ap, raw[j], pre_base[j]);
            v = 1.0f / (1.0f + expf(-v));
            pre[j] = v; sum += v;
        }
        float inv = 1.0f / (sum + EPSV);

        float post[4];
        #pragma unroll
        for (int j = 0; j < 4; j++) {
            float v = fmaf(apo, raw[4 + j], post_base[j]);
            post[j] = 2.0f / (1.0f + expf(-v));
        }

        float P[16];
        #pragma unroll
        for (int j = 0; j < 16; j++)
            P[j] = fabsf(fmaf(ar, raw[8 + j], res_base[j])) + EPSV;
        for (int it = 0; it < 20; it++) {
            #pragma unroll
            for (int r = 0; r < 4; r++) {
                float rs = (P[4*r] + P[4*r+1]) + (P[4*r+2] + P[4*r+3]) + EPSV;
                float ir = 1.0f / rs;
                P[4*r] *= ir; P[4*r+1] *= ir; P[4*r+2] *= ir; P[4*r+3] *= ir;
            }
            #pragma unroll
            for (int cI = 0; cI < 4; cI++) {
                float cs = (P[cI] + P[4+cI]) + (P[8+cI] + P[12+cI]) + EPSV;
                float ic = 1.0f / cs;
                P[cI] *= ic; P[4+cI] *= ic; P[8+cI] *= ic; P[12+cI] *= ic;
            }
        }

        float* o = &g_coefs[bb * 24];
        #pragma unroll
        for (int j = 0; j < 4; j++)  o[j]     = pre[j] * inv;
        #pragma unroll
        for (int j = 0; j < 4; j++)  o[4 + j] = post[j];
        #pragma unroll
        for (int j = 0; j < 16; j++) o[8 + j] = P[j];
    }
}

// ---------------------------------------------------------------------------
// Kernel 3: stream mixing + residual + pack.  (R2-exact: measured 95us, ~80% DRAM)
// grid = 16384 (b*s), block = 256 (one float4 of d per thread)
// ---------------------------------------------------------------------------
__global__ __launch_bounds__(256) void k_mix(const float4* __restrict__ H4,
                                             const float4* __restrict__ BO4,
                                             float4* __restrict__ out4) {
    __shared__ float c[24];
    const int bs = blockIdx.x;          // b*4096 + s
    const int b  = bs >> 12;
    const int t  = threadIdx.x;
    if (t < 24) c[t] = g_coefs[b * 24 + t];
    __syncthreads();

    const size_t hb = (size_t)bs * (NSTR * D4) + t;
    float4 h0 = H4[hb];
    float4 h1 = H4[hb + D4];
    float4 h2 = H4[hb + 2 * D4];
    float4 h3 = H4[hb + 3 * D4];
    float4 bo = BO4[(size_t)bs * D4 + t];

    const size_t ob = (size_t)bs * (5 * D4) + t;

    float4 r;
    r.x = fmaf(c[0], h0.x, fmaf(c[1], h1.x, fmaf(c[2], h2.x, c[3] * h3.x)));
    r.y = fmaf(c[0], h0.y, fmaf(c[1], h1.y, fmaf(c[2], h2.y, c[3] * h3.y)));
    r.z = fmaf(c[0], h0.z, fmaf(c[1], h1.z, fmaf(c[2], h2.z, c[3] * h3.z)));
    r.w = fmaf(c[0], h0.w, fmaf(c[1], h1.w, fmaf(c[2], h2.w, c[3] * h3.w)));
    out4[ob] = r;

    #pragma unroll
    for (int n = 0; n < 4; n++) {
        float r0 = c[8 + 4*n], r1 = c[9 + 4*n], r2 = c[10 + 4*n], r3 = c[11 + 4*n];
        float pp = c[4 + n];
        float4 o;
        o.x = fmaf(r0, h0.x, fmaf(r1, h1.x, fmaf(r2, h2.x, fmaf(r3, h3.x, pp * bo.x))));
        o.y = fmaf(r0, h0.y, fmaf(r1, h1.y, fmaf(r2, h2.y, fmaf(r3, h3.y, pp * bo.y))));
        o.z = fmaf(r0, h0.z, fmaf(r1, h1.z, fmaf(r2, h2.z, fmaf(r3, h3.z, pp * bo.z))));
        o.w = fmaf(r0, h0.w, fmaf(r1, h1.w, fmaf(r2, h2.w, fmaf(r3, h3.w, pp * bo.w))));
        out4[ob + (size_t)(1 + n) * D4] = o;
    }
}

// ---------------------------------------------------------------------------
// Inputs (metadata order): H, branch_output, phi, H_pre_base, H_post_base,
//                          H_res_base, alpha_pre, alpha_post, alpha_res
// ---------------------------------------------------------------------------
extern "C" void kernel_launch(void* const* d_in, const int* in_sizes, int n_in,
                              void* d_out, int out_size) {
    (void)in_sizes; (void)n_in; (void)out_size;
    const float4* H4  = (const float4*)d_in[0];
    const float4* BO4 = (const float4*)d_in[1];
    const float* phi  = (const float*)d_in[2];
    const float* preb = (const float*)d_in[3];
    const float* postb= (const float*)d_in[4];
    const float* resb = (const float*)d_in[5];
    const float* apre = (const float*)d_in[6];
    const float* apost= (const float*)d_in[7];
    const float* ares = (const float*)d_in[8];

    dim3 g1(NCH, NSTR, NSTR);
    k_reduce1<<<g1, 256>>>(H4);
    k_coefs<<<NFB, 256>>>(phi, preb, postb, resb, apre, apost, ares);
    k_mix<<<16384, 256>>>(H4, BO4, (float4*)d_out);
}